// round 1
// baseline (speedup 1.0000x reference)
#include <cuda_runtime.h>
#include <math.h>

// ---------------- problem constants ----------------
#define CB    8
#define CL    4096
#define CN    32768          // CB*CL tokens
#define CDIM  512
#define CE    336
#define CH    6
#define CHD   56
#define CKC   819            // int(L*0.2)
#define CDD   256            // truncated SSM impulse-response length (exact to fp32)
#define CQK   1008           // 3*E

// ---------------- scratch (device globals; no allocation allowed) ----------------
__device__ float d_xp[(size_t)CN * CE];        // 44 MB
__device__ float d_rnorm[CN];
__device__ float d_qkv[(size_t)CN * CQK];      // 132 MB
__device__ float d_outE[(size_t)CN * CE];      // 44 MB
__device__ float d_imp[CN];
__device__ int   d_idx[CB * CKC];
__device__ float d_u[(size_t)CB * CKC * CE];   // conv output, layout (B, kc, E)
__device__ float d_g[CE * CDD];                // SSM impulse response per channel
__device__ float d_y[(size_t)CB * CKC * CE];   // SSM output, layout (B*kc, E)

// ---------------- copy x -> out ----------------
__global__ void copy_kernel(const float4* __restrict__ src, float4* __restrict__ dst, int n4) {
    int i = blockIdx.x * blockDim.x + threadIdx.x;
    if (i < n4) dst[i] = src[i];
}

// ---------------- generic tiled SGEMM, MODE: 0=DyT-A, 1=rowscale-A, 2=scatter-epilogue ----------------
template <int MODE>
__global__ __launch_bounds__(256) void sgemm_kernel(
    const float* __restrict__ A, const float* __restrict__ B,
    const float* __restrict__ bias, float* __restrict__ C,
    int M, int Nn, int K,
    const float* __restrict__ alphaP, const float* __restrict__ dytw, const float* __restrict__ dytb,
    const float* __restrict__ rowScale,
    const int* __restrict__ sIdx, const float* __restrict__ resid)
{
    constexpr int BM = 128, BN = 128, BK = 8;
    __shared__ float As[BK][BM];
    __shared__ float Bs[BK][BN];
    const int tid  = threadIdx.x;
    const int aRow = tid >> 1, aCol = (tid & 1) << 2;
    const int bRow = tid >> 5, bCol = (tid & 31) << 2;
    const int rowBase = blockIdx.y * BM, colBase = blockIdx.x * BN;
    const int tr = tid >> 4, tc = tid & 15;

    float acc[8][8];
#pragma unroll
    for (int i = 0; i < 8; i++)
#pragma unroll
        for (int j = 0; j < 8; j++) acc[i][j] = 0.f;

    const int gr = rowBase + aRow;
    float rs = 1.f;
    if (MODE == 1) rs = (gr < M) ? rowScale[gr] : 0.f;
    float al = 0.f;
    if (MODE == 0) al = alphaP[0];
    const float* Arow = A + (size_t)gr * K;

    for (int k0 = 0; k0 < K; k0 += BK) {
        float4 av = make_float4(0.f, 0.f, 0.f, 0.f);
        if (gr < M) {
            av = *(const float4*)(Arow + k0 + aCol);
            if (MODE == 0) {
                int kk0 = k0 + aCol;
                av.x = tanhf(al * av.x) * dytw[kk0 + 0] + dytb[kk0 + 0];
                av.y = tanhf(al * av.y) * dytw[kk0 + 1] + dytb[kk0 + 1];
                av.z = tanhf(al * av.z) * dytw[kk0 + 2] + dytb[kk0 + 2];
                av.w = tanhf(al * av.w) * dytw[kk0 + 3] + dytb[kk0 + 3];
            } else if (MODE == 1) {
                av.x *= rs; av.y *= rs; av.z *= rs; av.w *= rs;
            }
        }
        As[aCol + 0][aRow] = av.x;
        As[aCol + 1][aRow] = av.y;
        As[aCol + 2][aRow] = av.z;
        As[aCol + 3][aRow] = av.w;

        float4 bv = make_float4(0.f, 0.f, 0.f, 0.f);
        int gc = colBase + bCol;
        if (gc < Nn) bv = *(const float4*)(B + (size_t)(k0 + bRow) * Nn + gc);
        *(float4*)&Bs[bRow][bCol] = bv;

        __syncthreads();
#pragma unroll
        for (int kk = 0; kk < BK; kk++) {
            float4 a0 = *(float4*)&As[kk][tr * 8];
            float4 a1 = *(float4*)&As[kk][tr * 8 + 4];
            float4 b0 = *(float4*)&Bs[kk][tc * 8];
            float4 b1 = *(float4*)&Bs[kk][tc * 8 + 4];
            float ra[8] = {a0.x, a0.y, a0.z, a0.w, a1.x, a1.y, a1.z, a1.w};
            float rb[8] = {b0.x, b0.y, b0.z, b0.w, b1.x, b1.y, b1.z, b1.w};
#pragma unroll
            for (int i = 0; i < 8; i++)
#pragma unroll
                for (int j = 0; j < 8; j++) acc[i][j] += ra[i] * rb[j];
        }
        __syncthreads();
    }

#pragma unroll
    for (int i = 0; i < 8; i++) {
        int r = rowBase + tr * 8 + i;
        if (r >= M) continue;
        float* Crow;
        const float* Rrow = nullptr;
        if (MODE == 2) {
            int b = r / CKC;
            int t = r - b * CKC;
            int orow = b * CL + sIdx[b * CKC + t];
            Crow = C + (size_t)orow * Nn;
            Rrow = resid + (size_t)orow * Nn;
        } else {
            Crow = C + (size_t)r * Nn;
        }
#pragma unroll
        for (int j = 0; j < 8; j++) {
            int c = colBase + tc * 8 + j;
            if (c < Nn) {
                float v = acc[i][j] + bias[c];
                if (MODE == 2) v += Rrow[c];
                Crow[c] = v;
            }
        }
    }
}

// ---------------- per-row inverse L2 norm of xp ----------------
__global__ void rownorm_kernel() {
    int gidx = blockIdx.x * blockDim.x + threadIdx.x;
    int row = gidx >> 5, lane = gidx & 31;
    if (row >= CN) return;
    const float* xr = d_xp + (size_t)row * CE;
    float s = 0.f;
    for (int c = lane; c < CE; c += 32) { float v = xr[c]; s += v * v; }
#pragma unroll
    for (int o = 16; o; o >>= 1) s += __shfl_xor_sync(0xffffffffu, s, o);
    if (lane == 0) d_rnorm[row] = 1.f / fmaxf(sqrtf(s), 1e-12f);
}

// ---------------- per-token sparse attention: argmax over 6x6 scores, gather v ----------------
__global__ __launch_bounds__(256) void attn_kernel() {
    __shared__ float sqk[8][672];
    __shared__ float ssc[8][36];
    __shared__ int   sgs[8][6];
    int w = threadIdx.x >> 5, lane = threadIdx.x & 31;
    int n = blockIdx.x * 8 + w;
    const float* row = d_qkv + (size_t)n * CQK;
    for (int i = lane; i < 672; i += 32) sqk[w][i] = row[i];
    __syncwarp();
    for (int p = lane; p < 36; p += 32) {
        int h = p / 6, g = p % 6;
        const float* qp = &sqk[w][h * CHD];
        const float* kp = &sqk[w][CE + g * CHD];
        float s = 0.f;
#pragma unroll
        for (int d = 0; d < CHD; d++) s += qp[d] * kp[d];
        ssc[w][p] = s;
    }
    __syncwarp();
    if (lane < CH) {
        int bi = 0;
        float bv = ssc[w][lane * 6];
        for (int g = 1; g < 6; g++) {
            float v = ssc[w][lane * 6 + g];
            if (v > bv) { bv = v; bi = g; }   // strict >: matches top_k first-max tie-break
        }
        sgs[w][lane] = bi;
    }
    __syncwarp();
    const float* vrow = row + 2 * CE;
    float ss = 0.f;
    for (int c = lane; c < CE; c += 32) {
        int h = c % CH, d = c / CH;          // out[b,l, d*H+h] = v[n, g*(h), d]
        float val = vrow[sgs[w][h] * CHD + d];
        d_outE[(size_t)n * CE + c] = val;
        ss += val * val;
    }
#pragma unroll
    for (int o = 16; o; o >>= 1) ss += __shfl_xor_sync(0xffffffffu, ss, o);
    if (lane == 0) d_imp[n] = sqrtf(ss);
}

// ---------------- per-batch top-k (full bitonic sort, descending, stable ties) ----------------
__global__ __launch_bounds__(512) void topk_kernel() {
    __shared__ float sv[CL];
    __shared__ int   si[CL];
    int b = blockIdx.x;
    int tid = threadIdx.x;
    for (int i = tid; i < CL; i += blockDim.x) { sv[i] = d_imp[b * CL + i]; si[i] = i; }
    __syncthreads();
    for (int k = 2; k <= CL; k <<= 1) {
        for (int j = k >> 1; j > 0; j >>= 1) {
            for (int i = tid; i < CL; i += blockDim.x) {
                int ixj = i ^ j;
                if (ixj > i) {
                    float v1 = sv[i], v2 = sv[ixj];
                    int i1 = si[i], i2 = si[ixj];
                    bool up = ((i & k) == 0);
                    bool betterIxj = (v2 > v1) || (v2 == v1 && i2 < i1);
                    bool betterI   = (v1 > v2) || (v1 == v2 && i1 < i2);
                    bool doswap = up ? betterIxj : betterI;
                    if (doswap) { sv[i] = v2; sv[ixj] = v1; si[i] = i2; si[ixj] = i1; }
                }
            }
            __syncthreads();
        }
    }
    for (int t = tid; t < CKC; t += blockDim.x) d_idx[b * CKC + t] = si[t];
}

// ---------------- gather selected tokens + depthwise conv (len 4, left pad 3) ----------------
__global__ void gatherconv_kernel(const float* __restrict__ convw) {
    int e = blockIdx.x * 64 + threadIdx.x;
    int t = blockIdx.y * 4 + threadIdx.y;
    int b = blockIdx.z;
    if (e >= CE || t >= CKC) return;
    float acc = 0.f;
#pragma unroll
    for (int j = 0; j < 4; j++) {
        int s = t + j - 3;
        if (s >= 0) {
            int r = d_idx[b * CKC + s];
            acc += convw[e * 4 + j] * d_outE[(size_t)(b * CL + r) * CE + e];
        }
    }
    d_u[(size_t)(b * CKC + t) * CE + e] = acc;
}

// ---------------- precompute g[e][d] = sigC[e]^T A^d sigB via log-doubling (1 block) ----------------
__global__ __launch_bounds__(256) void gpre_kernel(const float* __restrict__ A,
                                                   const float* __restrict__ Bp,
                                                   const float* __restrict__ Cp) {
    __shared__ float Ms[256], Mt[256];
    __shared__ float Vs[CDD * 16];
    __shared__ float sC[CE * 16];
    int tid = threadIdx.x;
    Ms[tid] = A[tid];
    for (int i = tid; i < CE * 16; i += 256) sC[i] = 1.f / (1.f + expf(-Cp[i]));
    if (tid < 16) Vs[tid] = 1.f / (1.f + expf(-Bp[tid]));
    __syncthreads();
    int len = 1;
    while (len < CDD) {
        int take = min(len, CDD - len);
        for (int idx = tid; idx < take * 16; idx += 256) {
            int d = idx >> 4, i = idx & 15;
            float s = 0.f;
#pragma unroll
            for (int j = 0; j < 16; j++) s += Ms[i * 16 + j] * Vs[d * 16 + j];
            Vs[(len + d) * 16 + i] = s;
        }
        __syncthreads();
        {
            int i = tid >> 4, j = tid & 15;
            float s = 0.f;
#pragma unroll
            for (int t2 = 0; t2 < 16; t2++) s += Ms[i * 16 + t2] * Ms[t2 * 16 + j];
            Mt[tid] = s;
        }
        __syncthreads();
        Ms[tid] = Mt[tid];
        __syncthreads();
        len += take;
    }
    for (int idx = tid; idx < CE * CDD; idx += 256) {
        int e = idx / CDD, d = idx % CDD;
        float s = 0.f;
#pragma unroll
        for (int j = 0; j < 16; j++) s += sC[e * 16 + j] * Vs[d * 16 + j];
        d_g[idx] = s;
    }
}

// ---------------- SSM as causal convolution with kernel g (exact, parallel over t) ----------------
__global__ __launch_bounds__(256) void convscan_kernel() {
    __shared__ float su[CKC + 1];
    __shared__ float sg[CDD];
    int e = blockIdx.x % CE;
    int b = blockIdx.x / CE;
    int tid = threadIdx.x;
    for (int t = tid; t < CKC; t += 256) su[t] = d_u[(size_t)(b * CKC + t) * CE + e];
    for (int d = tid; d < CDD; d += 256) sg[d] = d_g[e * CDD + d];
    __syncthreads();
    for (int t = tid; t < CKC; t += 256) {
        int dmax = min(t, CDD - 1);
        float acc = 0.f;
        for (int d = 0; d <= dmax; d++) acc += sg[d] * su[t - d];
        d_y[(size_t)(b * CKC + t) * CE + e] = acc;
    }
}

// ---------------- launcher ----------------
extern "C" void kernel_launch(void* const* d_in, const int* in_sizes, int n_in,
                              void* d_out, int out_size) {
    const float* x      = (const float*)d_in[0];
    const float* alpha  = (const float*)d_in[1];
    const float* dyt_w  = (const float*)d_in[2];
    const float* dyt_b  = (const float*)d_in[3];
    const float* W_in   = (const float*)d_in[4];
    const float* b_in   = (const float*)d_in[5];
    const float* W_qkv  = (const float*)d_in[6];
    const float* b_qkv  = (const float*)d_in[7];
    const float* conv_w = (const float*)d_in[8];
    const float* A      = (const float*)d_in[9];
    const float* Bp     = (const float*)d_in[10];
    const float* Cp     = (const float*)d_in[11];
    const float* W_out  = (const float*)d_in[12];
    const float* b_out  = (const float*)d_in[13];
    float* out = (float*)d_out;

    void *p_xp, *p_rnorm, *p_qkv, *p_y, *p_idx;
    cudaGetSymbolAddress(&p_xp, d_xp);
    cudaGetSymbolAddress(&p_rnorm, d_rnorm);
    cudaGetSymbolAddress(&p_qkv, d_qkv);
    cudaGetSymbolAddress(&p_y, d_y);
    cudaGetSymbolAddress(&p_idx, d_idx);

    // 0) out = x
    {
        int n4 = (CN * CDIM) / 4;
        copy_kernel<<<(n4 + 255) / 256, 256>>>((const float4*)x, (float4*)out, n4);
    }
    // 1) SSM impulse response (independent; tiny)
    gpre_kernel<<<1, 256>>>(A, Bp, Cp);
    // 2) DyT + GEMM1 -> xp
    {
        dim3 grid((CE + 127) / 128, CN / 128);
        sgemm_kernel<0><<<grid, 256>>>(x, W_in, b_in, (float*)p_xp, CN, CE, CDIM,
                                       alpha, dyt_w, dyt_b, nullptr, nullptr, nullptr);
    }
    // 3) row norms
    rownorm_kernel<<<(CN * 32 + 255) / 256, 256>>>();
    // 4) GEMM2 (row-scaled A) -> qkv
    {
        dim3 grid((CQK + 127) / 128, CN / 128);
        sgemm_kernel<1><<<grid, 256>>>((const float*)p_xp, W_qkv, b_qkv, (float*)p_qkv,
                                       CN, CQK, CE, nullptr, nullptr, nullptr,
                                       (const float*)p_rnorm, nullptr, nullptr);
    }
    // 5) per-token attention -> outE, imp
    attn_kernel<<<CN / 8, 256>>>();
    // 6) per-batch top-k (ordered)
    topk_kernel<<<CB, 512>>>();
    // 7) gather + depthwise conv -> u
    {
        dim3 grid((CE + 63) / 64, (CKC + 3) / 4, CB);
        gatherconv_kernel<<<grid, dim3(64, 4)>>>(conv_w);
    }
    // 8) SSM via causal conv -> y
    convscan_kernel<<<CB * CE, 256>>>();
    // 9) GEMM3 + bias + residual + scatter into out
    {
        dim3 grid((CDIM + 127) / 128, (CB * CKC + 127) / 128);
        sgemm_kernel<2><<<grid, 256>>>((const float*)p_y, W_out, b_out, out,
                                       CB * CKC, CDIM, CE, nullptr, nullptr, nullptr,
                                       nullptr, (const int*)p_idx, x);
    }
}

// round 5
// speedup vs baseline: 1.0768x; 1.0768x over previous
#include <cuda_runtime.h>
#include <cuda_bf16.h>
#include <math.h>
#include <cstdint>

// ---------------- problem constants ----------------
#define CB    8
#define CL    4096
#define CN    32768          // CB*CL tokens
#define CDIM  512
#define CE    336
#define CH    6
#define CHD   56
#define CKC   819            // int(L*0.2)
#define CDD   256            // truncated SSM impulse-response length (exact to fp32)
#define CQK   1008           // 3*E

// ---------------- scratch (device globals; no allocation allowed) ----------------
__device__ float d_xp[(size_t)CN * CE];        // 44 MB
__device__ float d_rnorm[CN];
__device__ float d_qkv[(size_t)CN * CQK];      // 132 MB
__device__ float d_outE[(size_t)CN * CE];      // 44 MB
__device__ float d_imp[CN];
__device__ int   d_idx[CB * CKC];
__device__ float d_u[(size_t)CB * CKC * CE];   // conv output, layout (B, kc, E)
__device__ float d_g[CE * CDD];                // SSM impulse response per channel
__device__ float d_y[(size_t)CB * CKC * CE];   // SSM output, layout (B*kc, E)

// ================= warp-MMA helpers (baseline PTX, sm_80+) =================
__device__ __forceinline__ uint32_t smem_u32(const void* p) {
    uint32_t a;
    asm("{ .reg .u64 t; cvta.to.shared.u64 t, %1; cvt.u32.u64 %0, t; }" : "=r"(a) : "l"(p));
    return a;
}

__device__ __forceinline__ void ldsm_x4(uint32_t* r, uint32_t addr) {
    asm volatile("ldmatrix.sync.aligned.m8n8.x4.shared.b16 {%0,%1,%2,%3}, [%4];"
                 : "=r"(r[0]), "=r"(r[1]), "=r"(r[2]), "=r"(r[3]) : "r"(addr));
}

__device__ __forceinline__ void mma16816(float* c, const uint32_t* a, uint32_t b0, uint32_t b1) {
    asm volatile(
        "mma.sync.aligned.m16n8k16.row.col.f32.bf16.bf16.f32 "
        "{%0,%1,%2,%3}, {%4,%5,%6,%7}, {%8,%9}, {%0,%1,%2,%3};"
        : "+f"(c[0]), "+f"(c[1]), "+f"(c[2]), "+f"(c[3])
        : "r"(a[0]), "r"(a[1]), "r"(a[2]), "r"(a[3]), "r"(b0), "r"(b1));
}

// smem tile stride: 32 k-elements padded to 40 (row stride 80B: 16B-aligned rows
// for ldmatrix + conflict-free bank quads)
#define TSTRIDE 40
#define TILE_ELEMS (128 * TSTRIDE)

// splits: v = s0 + s1 (+ s2)
template <int NS>
__device__ __forceinline__ void split_bf16(float v, __nv_bfloat16* s) {
    float r = v;
    __nv_bfloat16 h0 = __float2bfloat16(r); s[0] = h0; r -= __bfloat162float(h0);
    __nv_bfloat16 h1 = __float2bfloat16(r); s[1] = h1;
    if (NS == 3) {
        r -= __bfloat162float(h1);
        s[2] = __float2bfloat16(r);
    }
}

// ================= HMMA GEMM: C[M,N] = A[M,K] @ B[K,N] ======================
// NSPLIT=3: 3-way bf16 split, 6 MMA terms (~fp32 accuracy) — feeds selections
// NSPLIT=2: 2-way bf16 split, 3 MMA terms (~2e-5)          — output-only GEMM
// MODE 0: A transformed by DyT (tanh(alpha*a)*w+b) during staging  -> GEMM1
// MODE 1: A scaled per-row by rowScale during staging              -> GEMM2
// MODE 2: epilogue scatter (C row = b*CL+idx) with residual add    -> GEMM3
template <int MODE, int NSPLIT>
__global__ __launch_bounds__(256, 2) void tc_gemm(
    const float* __restrict__ A, const float* __restrict__ B,
    const float* __restrict__ bias, float* __restrict__ C,
    int M, int N, int K,
    const float* __restrict__ alphaP, const float* __restrict__ dytw, const float* __restrict__ dytb,
    const float* __restrict__ rowScale,
    const int* __restrict__ sIdx, const float* __restrict__ resid)
{
    extern __shared__ __nv_bfloat16 smem[];
    // tile order: A splits [0..NSPLIT), then B splits
    __nv_bfloat16* As[NSPLIT];
    __nv_bfloat16* Bs[NSPLIT];
#pragma unroll
    for (int s = 0; s < NSPLIT; s++) {
        As[s] = smem + (size_t)s * TILE_ELEMS;
        Bs[s] = smem + (size_t)(NSPLIT + s) * TILE_ELEMS;
    }

    const int tid  = threadIdx.x;
    const int wid  = tid >> 5;
    const int lane = tid & 31;
    const int warp_m = wid >> 2;          // 0..1  (64 rows each)
    const int warp_n = wid & 3;           // 0..3  (32 cols each)

    const int rowBase = blockIdx.y * 128;
    const int colBase = blockIdx.x * 128;
    const float al = (MODE == 0) ? alphaP[0] : 0.f;

    float acc[4][4][4];
#pragma unroll
    for (int im = 0; im < 4; im++)
#pragma unroll
        for (int in = 0; in < 4; in++)
#pragma unroll
            for (int q = 0; q < 4; q++) acc[im][in][q] = 0.f;

    uint32_t aBase[NSPLIT], bBase[NSPLIT];
#pragma unroll
    for (int s = 0; s < NSPLIT; s++) { aBase[s] = smem_u32(As[s]); bBase[s] = smem_u32(Bs[s]); }

    const int nChunks = (K + 31) / 32;
    for (int c = 0; c < nChunks; c++) {
        const int k0 = c * 32;

        // ---- stage A tile: 128 rows x 32 k (as 16 k-pairs), split bf16 ----
#pragma unroll
        for (int i = 0; i < 8; i++) {
            int idx = i * 256 + tid;          // 0..2047
            int r = idx >> 4;                 // 0..127
            int kp = idx & 15;                // k-pair
            int gr = rowBase + r;
            int gk = k0 + kp * 2;
            float v0 = 0.f, v1 = 0.f;
            if (gr < M && gk < K) {
                const float2 va = *(const float2*)(A + (size_t)gr * K + gk);
                v0 = va.x; v1 = va.y;
                if (MODE == 0) {
                    v0 = tanhf(al * v0) * dytw[gk] + dytb[gk];
                    v1 = tanhf(al * v1) * dytw[gk + 1] + dytb[gk + 1];
                } else if (MODE == 1) {
                    float rs = rowScale[gr];
                    v0 *= rs; v1 *= rs;
                }
            }
            __nv_bfloat16 s0[3], s1[3];
            split_bf16<NSPLIT>(v0, s0);
            split_bf16<NSPLIT>(v1, s1);
            int so = r * TSTRIDE + kp * 2;
#pragma unroll
            for (int s = 0; s < NSPLIT; s++)
                *(__nv_bfloat162*)(As[s] + so) = __nv_bfloat162(s0[s], s1[s]);
        }
        // ---- stage B^T tile: Bs[n][k] = B[k][n], 128 n x 32 k ----
#pragma unroll
        for (int i = 0; i < 8; i++) {
            int idx = i * 256 + tid;          // 0..2047
            int n = idx & 127;
            int kp = idx >> 7;                // 0..15
            int gc = colBase + n;
            int gk = k0 + kp * 2;
            float v0 = 0.f, v1 = 0.f;
            if (gc < N) {
                if (gk < K)     v0 = B[(size_t)gk * N + gc];
                if (gk + 1 < K) v1 = B[(size_t)(gk + 1) * N + gc];
            }
            __nv_bfloat16 s0[3], s1[3];
            split_bf16<NSPLIT>(v0, s0);
            split_bf16<NSPLIT>(v1, s1);
            int so = n * TSTRIDE + kp * 2;
#pragma unroll
            for (int s = 0; s < NSPLIT; s++)
                *(__nv_bfloat162*)(Bs[s] + so) = __nv_bfloat162(s0[s], s1[s]);
        }
        __syncthreads();

        // ---- compute: 2 k-steps of 16 ----
#pragma unroll
        for (int ks = 0; ks < 2; ks++) {
            const uint32_t lrow = (uint32_t)(lane & 15);
            const uint32_t lkof = (uint32_t)((lane >> 4) * 8 + ks * 16);

            // B fragments resident: [in][split][2]
            uint32_t bf[4][NSPLIT][2];
#pragma unroll
            for (int p = 0; p < 2; p++) {
                uint32_t off = ((warp_n * 32 + p * 16 + lrow) * TSTRIDE + lkof) * 2;
#pragma unroll
                for (int s = 0; s < NSPLIT; s++) {
                    uint32_t t[4];
                    ldsm_x4(t, bBase[s] + off);
                    bf[2 * p][s][0] = t[0]; bf[2 * p][s][1] = t[2];
                    bf[2 * p + 1][s][0] = t[1]; bf[2 * p + 1][s][1] = t[3];
                }
            }
            // A fragments transient per im
#pragma unroll
            for (int im = 0; im < 4; im++) {
                uint32_t off = ((warp_m * 64 + im * 16 + lrow) * TSTRIDE + lkof) * 2;
                uint32_t af[NSPLIT][4];
#pragma unroll
                for (int s = 0; s < NSPLIT; s++) ldsm_x4(af[s], aBase[s] + off);
#pragma unroll
                for (int in = 0; in < 4; in++) {
                    // term (i,j): A split i with B split j; include all i+j <= NSPLIT-1... for
                    // NSPLIT=2: hh, hl, lh ; NSPLIT=3: hh, hm, mh, hl, mm, lh
                    mma16816(acc[im][in], af[0], bf[in][0][0], bf[in][0][1]);
                    mma16816(acc[im][in], af[0], bf[in][1][0], bf[in][1][1]);
                    mma16816(acc[im][in], af[1], bf[in][0][0], bf[in][0][1]);
                    if (NSPLIT == 3) {
                        mma16816(acc[im][in], af[0], bf[in][2][0], bf[in][2][1]);
                        mma16816(acc[im][in], af[1], bf[in][1][0], bf[in][1][1]);
                        mma16816(acc[im][in], af[2], bf[in][0][0], bf[in][0][1]);
                    }
                }
            }
        }
        __syncthreads();
    }

    // ---- epilogue ----
    const int colOff = colBase + warp_n * 32 + (lane & 3) * 2;
#pragma unroll
    for (int im = 0; im < 4; im++) {
        int r0 = rowBase + warp_m * 64 + im * 16 + (lane >> 2);
#pragma unroll
        for (int half = 0; half < 2; half++) {
            int r = r0 + half * 8;
            if (r >= M) continue;
            float* Crow;
            const float* Rrow = nullptr;
            if (MODE == 2) {
                int b = r / CKC;
                int t = r - b * CKC;
                int orow = b * CL + sIdx[b * CKC + t];
                Crow = C + (size_t)orow * N;
                Rrow = resid + (size_t)orow * N;
            } else {
                Crow = C + (size_t)r * N;
            }
#pragma unroll
            for (int in = 0; in < 4; in++) {
                int col = colOff + in * 8;
                if (col < N) {
                    float v0 = acc[im][in][half * 2 + 0] + bias[col];
                    float v1 = acc[im][in][half * 2 + 1] + bias[col + 1];
                    if (MODE == 2) { v0 += Rrow[col]; v1 += Rrow[col + 1]; }
                    *(float2*)(Crow + col) = make_float2(v0, v1);
                }
            }
        }
    }
}

// ---------------- copy x -> out ----------------
__global__ void copy_kernel(const float4* __restrict__ src, float4* __restrict__ dst, int n4) {
    int i = blockIdx.x * blockDim.x + threadIdx.x;
    if (i < n4) dst[i] = src[i];
}

// ---------------- per-row inverse L2 norm of xp ----------------
__global__ void rownorm_kernel() {
    int gidx = blockIdx.x * blockDim.x + threadIdx.x;
    int row = gidx >> 5, lane = gidx & 31;
    if (row >= CN) return;
    const float4* xr = (const float4*)(d_xp + (size_t)row * CE);   // 336 = 84 float4
    float s = 0.f;
    for (int c = lane; c < 84; c += 32) {
        float4 v = xr[c];
        s += v.x * v.x + v.y * v.y + v.z * v.z + v.w * v.w;
    }
#pragma unroll
    for (int o = 16; o; o >>= 1) s += __shfl_xor_sync(0xffffffffu, s, o);
    if (lane == 0) d_rnorm[row] = 1.f / fmaxf(sqrtf(s), 1e-12f);
}

// ---------------- per-token sparse attention: argmax over 6x6 scores, gather v ----------------
__global__ __launch_bounds__(256) void attn_kernel() {
    __shared__ float sqk[8][672];
    __shared__ float ssc[8][36];
    __shared__ int   sgs[8][6];
    int w = threadIdx.x >> 5, lane = threadIdx.x & 31;
    int n = blockIdx.x * 8 + w;
    const float* row = d_qkv + (size_t)n * CQK;
    for (int i = lane; i < 672; i += 32) sqk[w][i] = row[i];
    __syncwarp();
    for (int p = lane; p < 36; p += 32) {
        int h = p / 6, g = p % 6;
        const float* qp = &sqk[w][h * CHD];
        const float* kp = &sqk[w][CE + g * CHD];
        float s = 0.f;
#pragma unroll
        for (int d = 0; d < CHD; d++) s += qp[d] * kp[d];
        ssc[w][p] = s;
    }
    __syncwarp();
    if (lane < CH) {
        int bi = 0;
        float bv = ssc[w][lane * 6];
        for (int g = 1; g < 6; g++) {
            float v = ssc[w][lane * 6 + g];
            if (v > bv) { bv = v; bi = g; }
        }
        sgs[w][lane] = bi;
    }
    __syncwarp();
    const float* vrow = row + 2 * CE;
    float ss = 0.f;
    for (int c = lane; c < CE; c += 32) {
        int h = c % CH, d = c / CH;
        float val = vrow[sgs[w][h] * CHD + d];
        d_outE[(size_t)n * CE + c] = val;
        ss += val * val;
    }
#pragma unroll
    for (int o = 16; o; o >>= 1) ss += __shfl_xor_sync(0xffffffffu, ss, o);
    if (lane == 0) d_imp[n] = sqrtf(ss);
}

// ---------------- per-batch top-k (full bitonic sort, descending, stable ties) ----------------
__global__ __launch_bounds__(512) void topk_kernel() {
    __shared__ float sv[CL];
    __shared__ int   si[CL];
    int b = blockIdx.x;
    int tid = threadIdx.x;
    for (int i = tid; i < CL; i += blockDim.x) { sv[i] = d_imp[b * CL + i]; si[i] = i; }
    __syncthreads();
    for (int k = 2; k <= CL; k <<= 1) {
        for (int j = k >> 1; j > 0; j >>= 1) {
            for (int i = tid; i < CL; i += blockDim.x) {
                int ixj = i ^ j;
                if (ixj > i) {
                    float v1 = sv[i], v2 = sv[ixj];
                    int i1 = si[i], i2 = si[ixj];
                    bool up = ((i & k) == 0);
                    bool betterIxj = (v2 > v1) || (v2 == v1 && i2 < i1);
                    bool betterI   = (v1 > v2) || (v1 == v2 && i1 < i2);
                    bool doswap = up ? betterIxj : betterI;
                    if (doswap) { sv[i] = v2; sv[ixj] = v1; si[i] = i2; si[ixj] = i1; }
                }
            }
            __syncthreads();
        }
    }
    for (int t = tid; t < CKC; t += blockDim.x) d_idx[b * CKC + t] = si[t];
}

// ---------------- gather selected tokens + depthwise conv (len 4, left pad 3) ----------------
__global__ void gatherconv_kernel(const float* __restrict__ convw) {
    int e = blockIdx.x * 64 + threadIdx.x;
    int t = blockIdx.y * 4 + threadIdx.y;
    int b = blockIdx.z;
    if (e >= CE || t >= CKC) return;
    float acc = 0.f;
#pragma unroll
    for (int j = 0; j < 4; j++) {
        int s = t + j - 3;
        if (s >= 0) {
            int r = d_idx[b * CKC + s];
            acc += convw[e * 4 + j] * d_outE[(size_t)(b * CL + r) * CE + e];
        }
    }
    d_u[(size_t)(b * CKC + t) * CE + e] = acc;
}

// ---------------- precompute g[e][d] = sigC[e]^T A^d sigB via log-doubling (1 block) ----------------
__global__ __launch_bounds__(256) void gpre_kernel(const float* __restrict__ A,
                                                   const float* __restrict__ Bp,
                                                   const float* __restrict__ Cp) {
    __shared__ float Ms[256], Mt[256];
    __shared__ float Vs[CDD * 16];
    __shared__ float sC[CE * 16];
    int tid = threadIdx.x;
    Ms[tid] = A[tid];
    for (int i = tid; i < CE * 16; i += 256) sC[i] = 1.f / (1.f + expf(-Cp[i]));
    if (tid < 16) Vs[tid] = 1.f / (1.f + expf(-Bp[tid]));
    __syncthreads();
    int len = 1;
    while (len < CDD) {
        int take = min(len, CDD - len);
        for (int idx = tid; idx < take * 16; idx += 256) {
            int d = idx >> 4, i = idx & 15;
            float s = 0.f;
#pragma unroll
            for (int j = 0; j < 16; j++) s += Ms[i * 16 + j] * Vs[d * 16 + j];
            Vs[(len + d) * 16 + i] = s;
        }
        __syncthreads();
        {
            int i = tid >> 4, j = tid & 15;
            float s = 0.f;
#pragma unroll
            for (int t2 = 0; t2 < 16; t2++) s += Ms[i * 16 + t2] * Ms[t2 * 16 + j];
            Mt[tid] = s;
        }
        __syncthreads();
        Ms[tid] = Mt[tid];
        __syncthreads();
        len += take;
    }
    for (int idx = tid; idx < CE * CDD; idx += 256) {
        int e = idx / CDD, d = idx % CDD;
        float s = 0.f;
#pragma unroll
        for (int j = 0; j < 16; j++) s += sC[e * 16 + j] * Vs[d * 16 + j];
        d_g[idx] = s;
    }
}

// ---------------- SSM as causal convolution (register-blocked, 8 outputs/thread) ----------------
__global__ __launch_bounds__(128) void convscan_kernel() {
    __shared__ float su[CKC];
    __shared__ float sg[CDD];
    int e = blockIdx.x % CE;
    int b = blockIdx.x / CE;
    int tid = threadIdx.x;
    for (int t = tid; t < CKC; t += 128) su[t] = d_u[(size_t)(b * CKC + t) * CE + e];
    for (int d = tid; d < CDD; d += 128) sg[d] = d_g[e * CDD + d];
    __syncthreads();
    int t0 = tid * 8;
    if (t0 >= CKC) return;
    float w[8], acc[8];
#pragma unroll
    for (int j = 0; j < 8; j++) {
        int t = t0 + j;
        w[j] = (t < CKC) ? su[t] : 0.f;
        acc[j] = 0.f;
    }
    for (int d = 0; d < CDD; d++) {
        float g = sg[d];
#pragma unroll
        for (int j = 0; j < 8; j++) acc[j] += g * w[j];
#pragma unroll
        for (int j = 7; j > 0; j--) w[j] = w[j - 1];
        int src = t0 - d - 1;
        w[0] = (src >= 0) ? su[src] : 0.f;
    }
#pragma unroll
    for (int j = 0; j < 8; j++) {
        int t = t0 + j;
        if (t < CKC) d_y[(size_t)(b * CKC + t) * CE + e] = acc[j];
    }
}

// ---------------- launcher ----------------
extern "C" void kernel_launch(void* const* d_in, const int* in_sizes, int n_in,
                              void* d_out, int out_size) {
    const float* x      = (const float*)d_in[0];
    const float* alpha  = (const float*)d_in[1];
    const float* dyt_w  = (const float*)d_in[2];
    const float* dyt_b  = (const float*)d_in[3];
    const float* W_in   = (const float*)d_in[4];
    const float* b_in   = (const float*)d_in[5];
    const float* W_qkv  = (const float*)d_in[6];
    const float* b_qkv  = (const float*)d_in[7];
    const float* conv_w = (const float*)d_in[8];
    const float* A      = (const float*)d_in[9];
    const float* Bp     = (const float*)d_in[10];
    const float* Cp     = (const float*)d_in[11];
    const float* W_out  = (const float*)d_in[12];
    const float* b_out  = (const float*)d_in[13];
    float* out = (float*)d_out;

    void *p_xp, *p_rnorm, *p_qkv, *p_y, *p_idx;
    cudaGetSymbolAddress(&p_xp, d_xp);
    cudaGetSymbolAddress(&p_rnorm, d_rnorm);
    cudaGetSymbolAddress(&p_qkv, d_qkv);
    cudaGetSymbolAddress(&p_y, d_y);
    cudaGetSymbolAddress(&p_idx, d_idx);

    const int smem6 = 6 * TILE_ELEMS * (int)sizeof(__nv_bfloat16);   // 61440
    const int smem4 = 4 * TILE_ELEMS * (int)sizeof(__nv_bfloat16);   // 40960
    cudaFuncSetAttribute(tc_gemm<0, 3>, cudaFuncAttributeMaxDynamicSharedMemorySize, smem6);
    cudaFuncSetAttribute(tc_gemm<1, 3>, cudaFuncAttributeMaxDynamicSharedMemorySize, smem6);
    cudaFuncSetAttribute(tc_gemm<2, 2>, cudaFuncAttributeMaxDynamicSharedMemorySize, smem4);

    // 0) out = x
    {
        int n4 = (CN * CDIM) / 4;
        copy_kernel<<<(n4 + 255) / 256, 256>>>((const float4*)x, (float4*)out, n4);
    }
    // 1) SSM impulse response (independent; tiny)
    gpre_kernel<<<1, 256>>>(A, Bp, Cp);
    // 2) DyT + GEMM1 -> xp   (M=32768, N=336, K=512)  [high accuracy]
    {
        dim3 grid((CE + 127) / 128, CN / 128);
        tc_gemm<0, 3><<<grid, 256, smem6>>>(x, W_in, b_in, (float*)p_xp, CN, CE, CDIM,
                                            alpha, dyt_w, dyt_b, nullptr, nullptr, nullptr);
    }
    // 3) row norms
    rownorm_kernel<<<(CN * 32 + 255) / 256, 256>>>();
    // 4) GEMM2 (row-scaled A) -> qkv   (M=32768, N=1008, K=336)  [high accuracy]
    {
        dim3 grid((CQK + 127) / 128, CN / 128);
        tc_gemm<1, 3><<<grid, 256, smem6>>>((const float*)p_xp, W_qkv, b_qkv, (float*)p_qkv,
                                            CN, CQK, CE, nullptr, nullptr, nullptr,
                                            (const float*)p_rnorm, nullptr, nullptr);
    }
    // 5) per-token attention -> outE, imp
    attn_kernel<<<CN / 8, 256>>>();
    // 6) per-batch top-k (ordered)
    topk_kernel<<<CB, 512>>>();
    // 7) gather + depthwise conv -> u
    {
        dim3 grid((CE + 63) / 64, (CKC + 3) / 4, CB);
        gatherconv_kernel<<<grid, dim3(64, 4)>>>(conv_w);
    }
    // 8) SSM via causal conv -> y
    convscan_kernel<<<CB * CE, 128>>>();
    // 9) GEMM3 + bias + residual + scatter into out   (M=6552, N=512, K=336)  [fast]
    {
        dim3 grid((CDIM + 127) / 128, (CB * CKC + 127) / 128);
        tc_gemm<2, 2><<<grid, 256, smem4>>>((const float*)p_y, W_out, b_out, out,
                                            CB * CKC, CDIM, CE, nullptr, nullptr, nullptr,
                                            nullptr, (const int*)p_idx, x);
    }
}